// round 6
// baseline (speedup 1.0000x reference)
#include <cuda_runtime.h>
#include <cuda_bf16.h>
#include <cstdint>

#define B_SZ 8192
#define M_SZ 64
#define D_SZ 256
#define K1   1024   // Xc layout: [h_hi | r_hi | h_lo | r_lo]
#define K2   1536   // Wc layout: [W_hi | W_lo | W_hi]

// scratch (static device arrays — no allocation)
__device__ __align__(256) float          g_r[B_SZ * D_SZ];              // 8 MB
__device__ __align__(256) __nv_bfloat16  g_Xc[(size_t)B_SZ * K1];       // 16 MB
__device__ __align__(256) __nv_bfloat16  g_Wc[256 * K2];                // 768 KB

// ---------------------------------------------------------------------------
// cp.async helpers
// ---------------------------------------------------------------------------
__device__ __forceinline__ void cp_async16(void* smem_ptr, const void* gptr) {
    unsigned sa = (unsigned)__cvta_generic_to_shared(smem_ptr);
    asm volatile("cp.async.cg.shared.global [%0], [%1], 16;\n" :: "r"(sa), "l"(gptr));
}
__device__ __forceinline__ void cp_commit() {
    asm volatile("cp.async.commit_group;\n");
}
template<int N> __device__ __forceinline__ void cp_wait() {
    asm volatile("cp.async.wait_group %0;\n" :: "n"(N));
}

// ---------------------------------------------------------------------------
// Kernel A: ragged attention. Only valid chunks are loaded. CH=8, 3 slots,
// early prefetch, 2 barriers/chunk, warp-level (not per-thread) softmax.
// 25 KB smem -> 8 CTAs/SM.
// ---------------------------------------------------------------------------
#define CH 8

__global__ __launch_bounds__(256, 8)
void attn_r_kernel(const float* __restrict__ h_tilde,
                   const float* __restrict__ mem,
                   const int* __restrict__ lengths) {
    __shared__ __align__(16) float buf[3][CH * D_SZ];   // 3 x 8 KB
    __shared__ float s_sc[CH];

    const int b    = blockIdx.x;
    const int tid  = threadIdx.x;
    const int warp = tid >> 5;
    const int lane = tid & 31;
    const int len  = lengths[b];

    const float hv = h_tilde[(size_t)b * D_SZ + tid];
    float r = 0.f;

    if (len > 0) {
        const float* gm = mem + (size_t)b * M_SZ * D_SZ;
        // h segment this lane needs for scores (vectorized row loads)
        const float4* h4 = (const float4*)(h_tilde + (size_t)b * D_SZ);
        const float4 ha = h4[lane * 2];
        const float4 hb = h4[lane * 2 + 1];

        const int nch = (len + CH - 1) >> 3;

        // prime: chunks 0,1 -> slots 0,1 (one commit group per chunk)
#pragma unroll
        for (int p = 0; p < 2; ++p) {
            if (p < nch) {
                const float4* g4 = (const float4*)(gm + p * CH * D_SZ);
                float4* s4 = (float4*)buf[p];
                cp_async16(s4 + tid, g4 + tid);
                cp_async16(s4 + tid + 256, g4 + tid + 256);
            }
            cp_commit();
        }

        float racc = 0.f, Mrun = -3.0e38f, Srun = 0.f;

        for (int c = 0; c < nch; ++c) {
            cp_wait<1>();          // chunk c landed (c+1 may still fly)
            __syncthreads();       // visible to all; slot (c+2)%3 reader-free

            // early prefetch chunk c+2 into slot (c+2)%3
            const int pc = c + 2;
            if (pc < nch) {
                const float4* g4 = (const float4*)(gm + pc * CH * D_SZ);
                float4* s4 = (float4*)buf[pc % 3];
                cp_async16(s4 + tid, g4 + tid);
                cp_async16(s4 + tid + 256, g4 + tid + 256);
            }
            cp_commit();

            const float* bm = buf[c % 3];

            // score for row = warp (vector loads, h in registers)
            {
                const float4* row4 = (const float4*)(bm + warp * D_SZ);
                const float4 a = row4[lane * 2];
                const float4 bb = row4[lane * 2 + 1];
                float acc = a.x * ha.x;
                acc = fmaf(a.y, ha.y, acc);
                acc = fmaf(a.z, ha.z, acc);
                acc = fmaf(a.w, ha.w, acc);
                acc = fmaf(bb.x, hb.x, acc);
                acc = fmaf(bb.y, hb.y, acc);
                acc = fmaf(bb.z, hb.z, acc);
                acc = fmaf(bb.w, hb.w, acc);
#pragma unroll
                for (int off = 16; off; off >>= 1)
                    acc += __shfl_xor_sync(0xffffffffu, acc, off);
                if (lane == 0)
                    s_sc[warp] = (c * CH + warp < len) ? acc : -1e9f;
            }
            __syncthreads();

            // warp-level online softmax (each warp independently, lanes 0-7)
            float sc = (lane < CH) ? s_sc[lane] : -1e9f;
            float cmax = sc;
            cmax = fmaxf(cmax, __shfl_xor_sync(0xffffffffu, cmax, 1));
            cmax = fmaxf(cmax, __shfl_xor_sync(0xffffffffu, cmax, 2));
            cmax = fmaxf(cmax, __shfl_xor_sync(0xffffffffu, cmax, 4));
            cmax = __shfl_sync(0xffffffffu, cmax, 0);
            const float nM   = fmaxf(Mrun, cmax);
            const float corr = __expf(Mrun - nM);
            float e = (lane < CH) ? __expf(sc - nM) : 0.f;
            float cs = e;
            cs += __shfl_xor_sync(0xffffffffu, cs, 1);
            cs += __shfl_xor_sync(0xffffffffu, cs, 2);
            cs += __shfl_xor_sync(0xffffffffu, cs, 4);
            cs = __shfl_sync(0xffffffffu, cs, 0);
            Srun = Srun * corr + cs;
            Mrun = nM;

            const float w0 = __shfl_sync(0xffffffffu, e, 0);
            const float w1 = __shfl_sync(0xffffffffu, e, 1);
            const float w2 = __shfl_sync(0xffffffffu, e, 2);
            const float w3 = __shfl_sync(0xffffffffu, e, 3);
            const float w4 = __shfl_sync(0xffffffffu, e, 4);
            const float w5 = __shfl_sync(0xffffffffu, e, 5);
            const float w6 = __shfl_sync(0xffffffffu, e, 6);
            const float w7 = __shfl_sync(0xffffffffu, e, 7);

            float acc2 = w0 * bm[tid];
            acc2 = fmaf(w1, bm[1 * D_SZ + tid], acc2);
            acc2 = fmaf(w2, bm[2 * D_SZ + tid], acc2);
            acc2 = fmaf(w3, bm[3 * D_SZ + tid], acc2);
            acc2 = fmaf(w4, bm[4 * D_SZ + tid], acc2);
            acc2 = fmaf(w5, bm[5 * D_SZ + tid], acc2);
            acc2 = fmaf(w6, bm[6 * D_SZ + tid], acc2);
            acc2 = fmaf(w7, bm[7 * D_SZ + tid], acc2);
            racc = racc * corr + acc2;
        }
        r = racc / Srun;
    }

    g_r[(size_t)b * D_SZ + tid] = r;

    // Xc row: [h_hi | r_hi | h_lo | r_lo]
    const __nv_bfloat16 hh = __float2bfloat16_rn(hv);
    const __nv_bfloat16 hl = __float2bfloat16_rn(hv - __bfloat162float(hh));
    const __nv_bfloat16 rh = __float2bfloat16_rn(r);
    const __nv_bfloat16 rl = __float2bfloat16_rn(r - __bfloat162float(rh));
    __nv_bfloat16* xr = g_Xc + (size_t)b * K1;
    xr[tid]       = hh;
    xr[256 + tid] = rh;
    xr[512 + tid] = hl;
    xr[768 + tid] = rl;
}

// ---------------------------------------------------------------------------
// W conversion: Wc[n] = [hi(W) | lo(W) | hi(W)], W[n] = [Wg_w[n] | Ug_w[n]]
// ---------------------------------------------------------------------------
__global__ void conv_w_kernel(const float* __restrict__ Wg_w,
                              const float* __restrict__ Ug_w) {
    const int n   = blockIdx.x / 6;
    const int j   = (blockIdx.x % 6) * 256 + threadIdx.x;
    const int k   = j & 511;
    const int seg = j >> 9;
    const float w = (k < 256) ? Wg_w[n * 256 + k] : Ug_w[n * 256 + (k - 256)];
    const __nv_bfloat16 hi = __float2bfloat16_rn(w);
    const __nv_bfloat16 v  = (seg == 1)
        ? __float2bfloat16_rn(w - __bfloat162float(hi))
        : hi;
    g_Wc[n * K2 + j] = v;
}

// ---------------------------------------------------------------------------
// Kernel B: bf16 tensor-core GEMM, virtual K=1536 (A hi segment reused).
// BM=128, BN=128, BK=32, 512 threads (16 warps 4x4, warp tile 32x32).
// 3-stage cp.async pipeline, ONE barrier per k-tile. Dynamic smem 61.4 KB.
// ---------------------------------------------------------------------------
#define BM 128
#define BN 128
#define BK 32
#define LDSK 40          // bf16 elems per smem row (80 B), conflict-free
#define STG_ELEMS (BM * LDSK)   // 5120 per operand per stage

__device__ __forceinline__ void mma16816(float c[4], const uint32_t a[4],
                                         const uint32_t bq[2]) {
    asm volatile(
        "mma.sync.aligned.m16n8k16.row.col.f32.bf16.bf16.f32 "
        "{%0,%1,%2,%3}, {%4,%5,%6,%7}, {%8,%9}, {%0,%1,%2,%3};\n"
        : "+f"(c[0]), "+f"(c[1]), "+f"(c[2]), "+f"(c[3])
        : "r"(a[0]), "r"(a[1]), "r"(a[2]), "r"(a[3]), "r"(bq[0]), "r"(bq[1]));
}

// virtual k-tile -> A offset:  0..15: hi*Whi, 16..31: hi*Wlo, 32..47: lo*Whi
__device__ __forceinline__ int a_koff(int kt) {
    return (kt < 16) ? kt * BK : (kt < 32) ? (kt - 16) * BK
                                           : 512 + (kt - 32) * BK;
}

__global__ __launch_bounds__(512)
void gate_gemm_bf16(const float* __restrict__ h_tilde,
                    const float* __restrict__ Wg_b,
                    const float* __restrict__ Ug_b,
                    const float* __restrict__ b_g,
                    const int* __restrict__ lengths,
                    float* __restrict__ out) {
    extern __shared__ __align__(16) __nv_bfloat16 smem[];
    __nv_bfloat16* sA = smem;                       // 3 * 5120
    __nv_bfloat16* sB = smem + 3 * STG_ELEMS;       // 3 * 5120

    const int tid  = threadIdx.x;
    const int warp = tid >> 5;
    const int lane = tid & 31;
    const int g    = lane >> 2;
    const int t    = lane & 3;
    const int wm   = warp >> 2;       // 0..3
    const int wn   = warp & 3;        // 0..3
    const int bm0  = blockIdx.x * BM;
    const int bn0  = blockIdx.y * BN;

    float acc[2][4][4];
#pragma unroll
    for (int mt = 0; mt < 2; ++mt)
#pragma unroll
        for (int nt = 0; nt < 4; ++nt)
#pragma unroll
            for (int i = 0; i < 4; ++i) acc[mt][nt][i] = 0.f;

    const __nv_bfloat16* gA = g_Xc + (size_t)bm0 * K1;
    const __nv_bfloat16* gB = g_Wc + (size_t)bn0 * K2;

    const int lr = tid >> 2;      // 0..127 loader row
    const int lc = (tid & 3) * 8; // k sub-offset (bf16 elems)

    // prime k-tiles 0,1 into slots 0,1
#pragma unroll
    for (int p = 0; p < 2; ++p) {
        cp_async16(sA + p * STG_ELEMS + lr * LDSK + lc,
                   gA + (size_t)lr * K1 + a_koff(p) + lc);
        cp_async16(sB + p * STG_ELEMS + lr * LDSK + lc,
                   gB + (size_t)lr * K2 + p * BK + lc);
        cp_commit();
    }

    const int NKT = K2 / BK;   // 48
    for (int kt = 0; kt < NKT; ++kt) {
        cp_wait<1>();
        __syncthreads();   // tile kt visible; slot (kt+2)%3 reader-free

        const int pc = kt + 2;
        if (pc < NKT) {
            const int st = pc % 3;
            cp_async16(sA + st * STG_ELEMS + lr * LDSK + lc,
                       gA + (size_t)lr * K1 + a_koff(pc) + lc);
            cp_async16(sB + st * STG_ELEMS + lr * LDSK + lc,
                       gB + (size_t)lr * K2 + pc * BK + lc);
        }
        cp_commit();

        const __nv_bfloat16* A  = sA + (kt % 3) * STG_ELEMS;
        const __nv_bfloat16* Bs = sB + (kt % 3) * STG_ELEMS;

#pragma unroll
        for (int ks = 0; ks < 2; ++ks) {
            uint32_t af[2][4], bq[4][2];
#pragma unroll
            for (int mt = 0; mt < 2; ++mt) {
                const int idx0 = (wm * 32 + mt * 16 + g) * LDSK + ks * 16 + 2 * t;
                af[mt][0] = *(const uint32_t*)(A + idx0);
                af[mt][1] = *(const uint32_t*)(A + idx0 + 8 * LDSK);
                af[mt][2] = *(const uint32_t*)(A + idx0 + 8);
                af[mt][3] = *(const uint32_t*)(A + idx0 + 8 * LDSK + 8);
            }
#pragma unroll
            for (int nt = 0; nt < 4; ++nt) {
                const int idx = (wn * 32 + nt * 8 + g) * LDSK + ks * 16 + 2 * t;
                bq[nt][0] = *(const uint32_t*)(Bs + idx);
                bq[nt][1] = *(const uint32_t*)(Bs + idx + 8);
            }
#pragma unroll
            for (int mt = 0; mt < 2; ++mt)
#pragma unroll
                for (int nt = 0; nt < 4; ++nt)
                    mma16816(acc[mt][nt], af[mt], bq[nt]);
        }
    }

    // fused epilogue
#pragma unroll
    for (int nt = 0; nt < 4; ++nt) {
        const int n = bn0 + wn * 32 + nt * 8 + 2 * t;
        const float bi0 = Wg_b[n] + Ug_b[n] + b_g[n];
        const float bi1 = Wg_b[n + 1] + Ug_b[n + 1] + b_g[n + 1];
#pragma unroll
        for (int mt = 0; mt < 2; ++mt) {
#pragma unroll
            for (int h2 = 0; h2 < 2; ++h2) {
                const int row = bm0 + wm * 32 + mt * 16 + g + 8 * h2;
                const bool has = lengths[row] > 0;
                const size_t base = (size_t)row * D_SZ + n;
                const float2 rv = *(const float2*)(g_r + base);
                const float2 hv = *(const float2*)(h_tilde + base);
                const float z0 = acc[mt][nt][2 * h2 + 0] + bi0;
                const float z1 = acc[mt][nt][2 * h2 + 1] + bi1;
                const float g0 = 1.f / (1.f + __expf(-z0));
                const float g1 = 1.f / (1.f + __expf(-z1));
                const float o0 = has ? (g0 * rv.x + (1.f - g0) * hv.x) : hv.x;
                const float o1 = has ? (g1 * rv.y + (1.f - g1) * hv.y) : hv.y;
                *(float2*)(out + base) = make_float2(o0, o1);
            }
        }
    }
}

// ---------------------------------------------------------------------------
extern "C" void kernel_launch(void* const* d_in, const int* in_sizes, int n_in,
                              void* d_out, int out_size) {
    const float* h_tilde = (const float*)d_in[0];
    const float* mem     = (const float*)d_in[1];
    const int*   lengths = (const int*)d_in[2];
    const float* Wg_w    = (const float*)d_in[3];
    const float* Wg_b    = (const float*)d_in[4];
    const float* Ug_w    = (const float*)d_in[5];
    const float* Ug_b    = (const float*)d_in[6];
    const float* b_g     = (const float*)d_in[7];
    float* out = (float*)d_out;

    // attn FIRST (slot 0 is the one ncu captures)
    attn_r_kernel<<<B_SZ, 256>>>(h_tilde, mem, lengths);
    conv_w_kernel<<<1536, 256>>>(Wg_w, Ug_w);

    const int smem_b = 6 * STG_ELEMS * (int)sizeof(__nv_bfloat16);  // 61440
    cudaFuncSetAttribute(gate_gemm_bf16,
                         cudaFuncAttributeMaxDynamicSharedMemorySize, smem_b);
    dim3 gridB(B_SZ / BM, D_SZ / BN);   // 64 x 2
    gate_gemm_bf16<<<gridB, 512, smem_b>>>(h_tilde, Wg_b, Ug_b, b_g,
                                           lengths, out);
}

// round 7
// speedup vs baseline: 1.0360x; 1.0360x over previous
#include <cuda_runtime.h>
#include <cuda_bf16.h>
#include <cstdint>

#define B_SZ 8192
#define M_SZ 64
#define D_SZ 256
#define K1   1024   // Xc layout: [h_hi | r_hi | h_lo | r_lo]
#define K2   1536   // Wc layout: [W_hi | W_lo | W_hi]
#define CH   8

// scratch (static device arrays — no allocation)
__device__ __align__(256) float          g_r[B_SZ * D_SZ];              // 8 MB
__device__ __align__(256) __nv_bfloat16  g_Xc[(size_t)B_SZ * K1];       // 16 MB
__device__ __align__(256) __nv_bfloat16  g_Wc[256 * K2];                // 768 KB

// ---------------------------------------------------------------------------
// helpers
// ---------------------------------------------------------------------------
__device__ __forceinline__ void cp_async16(void* smem_ptr, const void* gptr) {
    unsigned sa = (unsigned)__cvta_generic_to_shared(smem_ptr);
    asm volatile("cp.async.cg.shared.global [%0], [%1], 16;\n" :: "r"(sa), "l"(gptr));
}
__device__ __forceinline__ void cp_commit() {
    asm volatile("cp.async.commit_group;\n");
}
template<int N> __device__ __forceinline__ void cp_wait() {
    asm volatile("cp.async.wait_group %0;\n" :: "n"(N));
}
__device__ __forceinline__ void ldsm_x4(uint32_t r[4], const void* p) {
    unsigned a = (unsigned)__cvta_generic_to_shared(p);
    asm volatile("ldmatrix.sync.aligned.m8n8.x4.shared.b16 {%0,%1,%2,%3}, [%4];"
                 : "=r"(r[0]), "=r"(r[1]), "=r"(r[2]), "=r"(r[3]) : "r"(a));
}

// ---------------------------------------------------------------------------
// Kernel A: ragged attention, register-resident rows (NO smem staging of mem).
// Warp w owns row c*8+w of each chunk: LDG.128 straight to registers, row used
// for both score and weighted accumulation. One barrier per chunk.
// Also folds the W hi/lo bf16 conversion (blocks 0..1535).
// ---------------------------------------------------------------------------
__global__ __launch_bounds__(256, 6)
void attn_r_kernel(const float* __restrict__ h_tilde,
                   const float* __restrict__ mem,
                   const int* __restrict__ lengths,
                   const float* __restrict__ Wg_w,
                   const float* __restrict__ Ug_w) {
    __shared__ float s_h[D_SZ];
    __shared__ float s_sc[2][CH];
    __shared__ float s_red[8 * D_SZ];   // 8 KB cross-warp reduce

    const int b    = blockIdx.x;
    const int tid  = threadIdx.x;
    const int warp = tid >> 5;
    const int lane = tid & 31;
    const int len  = lengths[b];

    const float hv = h_tilde[(size_t)b * D_SZ + tid];
    s_h[tid] = hv;

    // folded W conversion (tiny, amortized over 1536 of 8192 blocks)
    if (b < 1536) {
        const int n   = b / 6;
        const int j   = (b % 6) * 256 + tid;
        const int k   = j & 511;
        const int seg = j >> 9;
        const float w = (k < 256) ? Wg_w[n * 256 + k] : Ug_w[n * 256 + (k - 256)];
        const __nv_bfloat16 hi = __float2bfloat16_rn(w);
        g_Wc[n * K2 + j] = (seg == 1)
            ? __float2bfloat16_rn(w - __bfloat162float(hi)) : hi;
    }
    __syncthreads();

    float r = 0.f;
    if (len > 0) {
        const float4* h4 = (const float4*)s_h;
        const int nch = (len + CH - 1) >> 3;

        float4 ra = make_float4(0.f, 0.f, 0.f, 0.f);
        float4 rb = make_float4(0.f, 0.f, 0.f, 0.f);
        float Mrun = -3.0e38f, Srun = 0.f;

        for (int c = 0; c < nch; ++c) {
            const int m = c * CH + warp;
            float4 a  = make_float4(0.f, 0.f, 0.f, 0.f);
            float4 bb = make_float4(0.f, 0.f, 0.f, 0.f);
            if (m < len) {
                const float4* row4 =
                    (const float4*)(mem + ((size_t)b * M_SZ + m) * D_SZ);
                a  = row4[lane * 2];
                bb = row4[lane * 2 + 1];
            }
            const float4 ha = h4[lane * 2];
            const float4 hb = h4[lane * 2 + 1];

            float acc = a.x * ha.x;
            acc = fmaf(a.y, ha.y, acc);
            acc = fmaf(a.z, ha.z, acc);
            acc = fmaf(a.w, ha.w, acc);
            acc = fmaf(bb.x, hb.x, acc);
            acc = fmaf(bb.y, hb.y, acc);
            acc = fmaf(bb.z, hb.z, acc);
            acc = fmaf(bb.w, hb.w, acc);
#pragma unroll
            for (int off = 16; off; off >>= 1)
                acc += __shfl_xor_sync(0xffffffffu, acc, off);
            if (lane == 0)
                s_sc[c & 1][warp] = (m < len) ? acc : -1e9f;
            __syncthreads();

            // softmax update (every lane; groups of 8 lanes span all 8 scores)
            const float sc = s_sc[c & 1][lane & 7];
            float cmax = sc;
            cmax = fmaxf(cmax, __shfl_xor_sync(0xffffffffu, cmax, 1));
            cmax = fmaxf(cmax, __shfl_xor_sync(0xffffffffu, cmax, 2));
            cmax = fmaxf(cmax, __shfl_xor_sync(0xffffffffu, cmax, 4));
            const float nM   = fmaxf(Mrun, cmax);
            const float corr = __expf(Mrun - nM);
            float e = __expf(sc - nM);
            float cs = e;
            cs += __shfl_xor_sync(0xffffffffu, cs, 1);
            cs += __shfl_xor_sync(0xffffffffu, cs, 2);
            cs += __shfl_xor_sync(0xffffffffu, cs, 4);
            Srun = Srun * corr + cs;
            Mrun = nM;

            // this warp's own row weight
            const float ew = __expf(s_sc[c & 1][warp] - nM);
            ra.x = fmaf(ew, a.x, ra.x * corr);
            ra.y = fmaf(ew, a.y, ra.y * corr);
            ra.z = fmaf(ew, a.z, ra.z * corr);
            ra.w = fmaf(ew, a.w, ra.w * corr);
            rb.x = fmaf(ew, bb.x, rb.x * corr);
            rb.y = fmaf(ew, bb.y, rb.y * corr);
            rb.z = fmaf(ew, bb.z, rb.z * corr);
            rb.w = fmaf(ew, bb.w, rb.w * corr);
        }

        // cross-warp column reduce via smem (one time)
        float4* red4 = (float4*)s_red;
        red4[warp * 64 + lane * 2]     = ra;
        red4[warp * 64 + lane * 2 + 1] = rb;
        __syncthreads();
        float sum = 0.f;
#pragma unroll
        for (int w = 0; w < 8; ++w)
            sum += s_red[w * D_SZ + tid];
        r = sum / Srun;
    }

    g_r[(size_t)b * D_SZ + tid] = r;

    // Xc row: [h_hi | r_hi | h_lo | r_lo]
    const __nv_bfloat16 hh = __float2bfloat16_rn(hv);
    const __nv_bfloat16 hl = __float2bfloat16_rn(hv - __bfloat162float(hh));
    const __nv_bfloat16 rh = __float2bfloat16_rn(r);
    const __nv_bfloat16 rl = __float2bfloat16_rn(r - __bfloat162float(rh));
    __nv_bfloat16* xr = g_Xc + (size_t)b * K1;
    xr[tid]       = hh;
    xr[256 + tid] = rh;
    xr[512 + tid] = hl;
    xr[768 + tid] = rl;
}

// ---------------------------------------------------------------------------
// Kernel B: bf16 tensor-core GEMM, virtual K=1536, ldmatrix fragment loads.
// BM=128, BN=64, BK=32, 256 threads (8 warps: 4 wm x 2 wn, warp tile 32x32).
// 3-stage cp.async pipeline, one barrier per k-tile. grid 64x4 = 256 CTAs.
// ---------------------------------------------------------------------------
#define BM 128
#define BN 64
#define BK 32
#define LDSK 40                 // bf16 elems per smem row (80 B)
#define STG_A (BM * LDSK)       // 5120
#define STG_B (BN * LDSK)       // 2560

__device__ __forceinline__ void mma16816(float c[4], const uint32_t a[4],
                                         const uint32_t b0, const uint32_t b1) {
    asm volatile(
        "mma.sync.aligned.m16n8k16.row.col.f32.bf16.bf16.f32 "
        "{%0,%1,%2,%3}, {%4,%5,%6,%7}, {%8,%9}, {%0,%1,%2,%3};\n"
        : "+f"(c[0]), "+f"(c[1]), "+f"(c[2]), "+f"(c[3])
        : "r"(a[0]), "r"(a[1]), "r"(a[2]), "r"(a[3]), "r"(b0), "r"(b1));
}

// virtual k-tile -> A offset:  0..15: hi*Whi, 16..31: hi*Wlo, 32..47: lo*Whi
__device__ __forceinline__ int a_koff(int kt) {
    return (kt < 16) ? kt * BK : (kt < 32) ? (kt - 16) * BK
                                           : 512 + (kt - 32) * BK;
}

__global__ __launch_bounds__(256)
void gate_gemm_bf16(const float* __restrict__ h_tilde,
                    const float* __restrict__ Wg_b,
                    const float* __restrict__ Ug_b,
                    const float* __restrict__ b_g,
                    const int* __restrict__ lengths,
                    float* __restrict__ out) {
    __shared__ __align__(16) __nv_bfloat16 sA[3 * STG_A];
    __shared__ __align__(16) __nv_bfloat16 sB[3 * STG_B];

    const int tid  = threadIdx.x;
    const int warp = tid >> 5;
    const int lane = tid & 31;
    const int g    = lane >> 2;
    const int t    = lane & 3;
    const int wm   = warp >> 1;       // 0..3
    const int wn   = warp & 1;        // 0..1
    const int bm0  = blockIdx.x * BM;
    const int bn0  = blockIdx.y * BN;

    float acc[2][4][4];
#pragma unroll
    for (int mt = 0; mt < 2; ++mt)
#pragma unroll
        for (int nt = 0; nt < 4; ++nt)
#pragma unroll
            for (int i = 0; i < 4; ++i) acc[mt][nt][i] = 0.f;

    const __nv_bfloat16* gA = g_Xc + (size_t)bm0 * K1;
    const __nv_bfloat16* gB = g_Wc + (size_t)bn0 * K2;

    // loaders: A two cp/thread, B one cp/thread
    const int ar0 = tid >> 2,          ac0 = (tid & 3) * 8;
    const int ar1 = (tid + 256) >> 2,  ac1 = (tid & 3) * 8;
    const int br  = tid >> 2,          bc  = (tid & 3) * 8;

    // prime k-tiles 0,1 into slots 0,1
#pragma unroll
    for (int p = 0; p < 2; ++p) {
        const int ao = a_koff(p);
        cp_async16(sA + p * STG_A + ar0 * LDSK + ac0, gA + (size_t)ar0 * K1 + ao + ac0);
        cp_async16(sA + p * STG_A + ar1 * LDSK + ac1, gA + (size_t)ar1 * K1 + ao + ac1);
        cp_async16(sB + p * STG_B + br * LDSK + bc,   gB + (size_t)br * K2 + p * BK + bc);
        cp_commit();
    }

    const int lmrow = lane & 15;
    const int lmcol = (lane >> 4) * 8;

    const int NKT = K2 / BK;   // 48
    for (int kt = 0; kt < NKT; ++kt) {
        cp_wait<1>();
        __syncthreads();   // tile kt visible; slot (kt+2)%3 reader-free

        const int pc = kt + 2;
        if (pc < NKT) {
            const int st = pc % 3;
            const int ao = a_koff(pc);
            cp_async16(sA + st * STG_A + ar0 * LDSK + ac0, gA + (size_t)ar0 * K1 + ao + ac0);
            cp_async16(sA + st * STG_A + ar1 * LDSK + ac1, gA + (size_t)ar1 * K1 + ao + ac1);
            cp_async16(sB + st * STG_B + br * LDSK + bc,   gB + (size_t)br * K2 + pc * BK + bc);
        }
        cp_commit();

        const __nv_bfloat16* A  = sA + (kt % 3) * STG_A;
        const __nv_bfloat16* Bs = sB + (kt % 3) * STG_B;

#pragma unroll
        for (int ks = 0; ks < 2; ++ks) {
            uint32_t af[2][4], bf[2][4];
#pragma unroll
            for (int mt = 0; mt < 2; ++mt)
                ldsm_x4(af[mt],
                        A + (wm * 32 + mt * 16 + lmrow) * LDSK + ks * 16 + lmcol);
#pragma unroll
            for (int j = 0; j < 2; ++j)
                ldsm_x4(bf[j],
                        Bs + (wn * 32 + j * 16 + lmrow) * LDSK + ks * 16 + lmcol);
#pragma unroll
            for (int mt = 0; mt < 2; ++mt) {
#pragma unroll
                for (int j = 0; j < 2; ++j) {
                    mma16816(acc[mt][2 * j],     af[mt], bf[j][0], bf[j][2]);
                    mma16816(acc[mt][2 * j + 1], af[mt], bf[j][1], bf[j][3]);
                }
            }
        }
    }

    // fused epilogue
#pragma unroll
    for (int nt = 0; nt < 4; ++nt) {
        const int n = bn0 + wn * 32 + nt * 8 + 2 * t;
        const float bi0 = Wg_b[n] + Ug_b[n] + b_g[n];
        const float bi1 = Wg_b[n + 1] + Ug_b[n + 1] + b_g[n + 1];
#pragma unroll
        for (int mt = 0; mt < 2; ++mt) {
#pragma unroll
            for (int h2 = 0; h2 < 2; ++h2) {
                const int row = bm0 + wm * 32 + mt * 16 + g + 8 * h2;
                const bool has = lengths[row] > 0;
                const size_t base = (size_t)row * D_SZ + n;
                const float2 rv = *(const float2*)(g_r + base);
                const float2 hv = *(const float2*)(h_tilde + base);
                const float z0 = acc[mt][nt][2 * h2 + 0] + bi0;
                const float z1 = acc[mt][nt][2 * h2 + 1] + bi1;
                const float g0 = 1.f / (1.f + __expf(-z0));
                const float g1 = 1.f / (1.f + __expf(-z1));
                const float o0 = has ? (g0 * rv.x + (1.f - g0) * hv.x) : hv.x;
                const float o1 = has ? (g1 * rv.y + (1.f - g1) * hv.y) : hv.y;
                *(float2*)(out + base) = make_float2(o0, o1);
            }
        }
    }
}

// ---------------------------------------------------------------------------
extern "C" void kernel_launch(void* const* d_in, const int* in_sizes, int n_in,
                              void* d_out, int out_size) {
    const float* h_tilde = (const float*)d_in[0];
    const float* mem     = (const float*)d_in[1];
    const int*   lengths = (const int*)d_in[2];
    const float* Wg_w    = (const float*)d_in[3];
    const float* Wg_b    = (const float*)d_in[4];
    const float* Ug_w    = (const float*)d_in[5];
    const float* Ug_b    = (const float*)d_in[6];
    const float* b_g     = (const float*)d_in[7];
    float* out = (float*)d_out;

    attn_r_kernel<<<B_SZ, 256>>>(h_tilde, mem, lengths, Wg_w, Ug_w);

    dim3 gridB(B_SZ / BM, D_SZ / BN);   // 64 x 4
    gate_gemm_bf16<<<gridB, 256>>>(h_tilde, Wg_b, Ug_b, b_g, lengths, out);
}

// round 8
// speedup vs baseline: 1.1681x; 1.1274x over previous
#include <cuda_runtime.h>
#include <cuda_bf16.h>
#include <cstdint>

#define B_SZ 8192
#define M_SZ 64
#define D_SZ 256
#define K1   1024   // Xc layout: [h_hi | r_hi | h_lo | r_lo]
#define K2   1536   // Wc layout: [W_hi | W_lo | W_hi]

// scratch (static device arrays — no allocation)
__device__ __align__(256) float          g_r[B_SZ * D_SZ];              // 8 MB
__device__ __align__(256) __nv_bfloat16  g_Xc[(size_t)B_SZ * K1];       // 16 MB
__device__ __align__(256) __nv_bfloat16  g_Wc[256 * K2];                // 768 KB

// ---------------------------------------------------------------------------
// helpers
// ---------------------------------------------------------------------------
__device__ __forceinline__ void cp_async16(void* smem_ptr, const void* gptr) {
    unsigned sa = (unsigned)__cvta_generic_to_shared(smem_ptr);
    asm volatile("cp.async.cg.shared.global [%0], [%1], 16;\n" :: "r"(sa), "l"(gptr));
}
__device__ __forceinline__ void cp_commit() {
    asm volatile("cp.async.commit_group;\n");
}
template<int N> __device__ __forceinline__ void cp_wait() {
    asm volatile("cp.async.wait_group %0;\n" :: "n"(N));
}
__device__ __forceinline__ void ldsm_x4(uint32_t r[4], const void* p) {
    unsigned a = (unsigned)__cvta_generic_to_shared(p);
    asm volatile("ldmatrix.sync.aligned.m8n8.x4.shared.b16 {%0,%1,%2,%3}, [%4];"
                 : "=r"(r[0]), "=r"(r[1]), "=r"(r[2]), "=r"(r[3]) : "r"(a));
}
__device__ __forceinline__ uint32_t packbf2(float x, float y) {
    __nv_bfloat162 t = __floats2bfloat162_rn(x, y);
    return *(uint32_t*)&t;
}

// ---------------------------------------------------------------------------
// Kernel A: warp-per-sample ragged attention. NO barriers, NO smem.
// Each warp owns one sample; rows in groups of 4, register double-buffered
// (loads for group g+1 in flight while computing group g). Online softmax.
// Blocks 0..1535 also fold the W hi/lo bf16 conversion (2 elems/thread).
// ---------------------------------------------------------------------------
struct Grp { float4 v[4][2]; };

__global__ __launch_bounds__(128, 4)
void attn_r_kernel(const float* __restrict__ h_tilde,
                   const float* __restrict__ mem,
                   const int* __restrict__ lengths,
                   const float* __restrict__ Wg_w,
                   const float* __restrict__ Ug_w) {
    const int tid  = threadIdx.x;
    const int warp = tid >> 5;
    const int lane = tid & 31;
    const int blk  = blockIdx.x;

    // folded W conversion
    if (blk < 1536) {
        const int n  = blk / 6;
        const int j0 = (blk % 6) * 256 + tid * 2;
#pragma unroll
        for (int u = 0; u < 2; ++u) {
            const int j   = j0 + u;
            const int k   = j & 511;
            const int seg = j >> 9;
            const float w = (k < 256) ? Wg_w[n * 256 + k]
                                      : Ug_w[n * 256 + (k - 256)];
            const __nv_bfloat16 hi = __float2bfloat16_rn(w);
            g_Wc[n * K2 + j] = (seg == 1)
                ? __float2bfloat16_rn(w - __bfloat162float(hi)) : hi;
        }
    }

    const int b   = blk * 4 + warp;
    const int len = lengths[b];

    const float4* hp = (const float4*)(h_tilde + (size_t)b * D_SZ);
    const float4 ha = hp[lane * 2];
    const float4 hb = hp[lane * 2 + 1];

    float4 r0 = make_float4(0.f, 0.f, 0.f, 0.f);
    float4 r1 = make_float4(0.f, 0.f, 0.f, 0.f);

    if (len > 0) {
        const float4* base = (const float4*)(mem + (size_t)b * M_SZ * D_SZ);
        float Mrun = -3.0e38f, Srun = 0.f;

        Grp A, Bf;

        auto loadg = [&](Grp& R, int g) {
#pragma unroll
            for (int i = 0; i < 4; ++i) {
                const int m = g * 4 + i;
                R.v[i][0] = make_float4(0.f, 0.f, 0.f, 0.f);
                R.v[i][1] = make_float4(0.f, 0.f, 0.f, 0.f);
                if (m < len) {
                    const float4* rp = base + (size_t)m * 64 + lane * 2;
                    R.v[i][0] = rp[0];
                    R.v[i][1] = rp[1];
                }
            }
        };

        auto process = [&](const Grp& R, int g) {
            float sc[4];
#pragma unroll
            for (int i = 0; i < 4; ++i) {
                const float4 a = R.v[i][0];
                const float4 c = R.v[i][1];
                float acc = a.x * ha.x;
                acc = fmaf(a.y, ha.y, acc);
                acc = fmaf(a.z, ha.z, acc);
                acc = fmaf(a.w, ha.w, acc);
                acc = fmaf(c.x, hb.x, acc);
                acc = fmaf(c.y, hb.y, acc);
                acc = fmaf(c.z, hb.z, acc);
                acc = fmaf(c.w, hb.w, acc);
#pragma unroll
                for (int off = 16; off; off >>= 1)
                    acc += __shfl_xor_sync(0xffffffffu, acc, off);
                sc[i] = (g * 4 + i < len) ? acc : -1e9f;
            }
            const float cmax = fmaxf(fmaxf(sc[0], sc[1]), fmaxf(sc[2], sc[3]));
            const float nM   = fmaxf(Mrun, cmax);
            const float corr = __expf(Mrun - nM);
            const float e0 = __expf(sc[0] - nM);
            const float e1 = __expf(sc[1] - nM);
            const float e2 = __expf(sc[2] - nM);
            const float e3 = __expf(sc[3] - nM);
            Srun = Srun * corr + (e0 + e1) + (e2 + e3);
            Mrun = nM;
            r0.x = fmaf(e0, R.v[0][0].x, fmaf(e1, R.v[1][0].x, fmaf(e2, R.v[2][0].x, fmaf(e3, R.v[3][0].x, r0.x * corr))));
            r0.y = fmaf(e0, R.v[0][0].y, fmaf(e1, R.v[1][0].y, fmaf(e2, R.v[2][0].y, fmaf(e3, R.v[3][0].y, r0.y * corr))));
            r0.z = fmaf(e0, R.v[0][0].z, fmaf(e1, R.v[1][0].z, fmaf(e2, R.v[2][0].z, fmaf(e3, R.v[3][0].z, r0.z * corr))));
            r0.w = fmaf(e0, R.v[0][0].w, fmaf(e1, R.v[1][0].w, fmaf(e2, R.v[2][0].w, fmaf(e3, R.v[3][0].w, r0.w * corr))));
            r1.x = fmaf(e0, R.v[0][1].x, fmaf(e1, R.v[1][1].x, fmaf(e2, R.v[2][1].x, fmaf(e3, R.v[3][1].x, r1.x * corr))));
            r1.y = fmaf(e0, R.v[0][1].y, fmaf(e1, R.v[1][1].y, fmaf(e2, R.v[2][1].y, fmaf(e3, R.v[3][1].y, r1.y * corr))));
            r1.z = fmaf(e0, R.v[0][1].z, fmaf(e1, R.v[1][1].z, fmaf(e2, R.v[2][1].z, fmaf(e3, R.v[3][1].z, r1.z * corr))));
            r1.w = fmaf(e0, R.v[0][1].w, fmaf(e1, R.v[1][1].w, fmaf(e2, R.v[2][1].w, fmaf(e3, R.v[3][1].w, r1.w * corr))));
        };

        const int ng = (len + 3) >> 2;
        loadg(A, 0);
        int g = 0;
        while (true) {
            if (g + 1 < ng) loadg(Bf, g + 1);
            process(A, g);
            ++g;
            if (g >= ng) break;
            if (g + 1 < ng) loadg(A, g + 1);
            process(Bf, g);
            ++g;
            if (g >= ng) break;
        }

        const float inv = 1.f / Srun;
        r0.x *= inv; r0.y *= inv; r0.z *= inv; r0.w *= inv;
        r1.x *= inv; r1.y *= inv; r1.z *= inv; r1.w *= inv;
    }

    // store r
    float* gr = g_r + (size_t)b * D_SZ + lane * 8;
    *(float4*)gr       = r0;
    *(float4*)(gr + 4) = r1;

    // emit Xc row: [h_hi | r_hi | h_lo | r_lo], 8 values/lane per segment
    float hvv[8] = {ha.x, ha.y, ha.z, ha.w, hb.x, hb.y, hb.z, hb.w};
    float rvv[8] = {r0.x, r0.y, r0.z, r0.w, r1.x, r1.y, r1.z, r1.w};
    float hlo[8], rlo[8];
#pragma unroll
    for (int i = 0; i < 8; ++i) {
        const __nv_bfloat16 hh = __float2bfloat16_rn(hvv[i]);
        const __nv_bfloat16 rh = __float2bfloat16_rn(rvv[i]);
        hlo[i] = hvv[i] - __bfloat162float(hh);
        rlo[i] = rvv[i] - __bfloat162float(rh);
    }
    __nv_bfloat16* xr = g_Xc + (size_t)b * K1 + lane * 8;
    uint4 p;
    p.x = packbf2(hvv[0], hvv[1]); p.y = packbf2(hvv[2], hvv[3]);
    p.z = packbf2(hvv[4], hvv[5]); p.w = packbf2(hvv[6], hvv[7]);
    *(uint4*)(xr) = p;
    p.x = packbf2(rvv[0], rvv[1]); p.y = packbf2(rvv[2], rvv[3]);
    p.z = packbf2(rvv[4], rvv[5]); p.w = packbf2(rvv[6], rvv[7]);
    *(uint4*)(xr + 256) = p;
    p.x = packbf2(hlo[0], hlo[1]); p.y = packbf2(hlo[2], hlo[3]);
    p.z = packbf2(hlo[4], hlo[5]); p.w = packbf2(hlo[6], hlo[7]);
    *(uint4*)(xr + 512) = p;
    p.x = packbf2(rlo[0], rlo[1]); p.y = packbf2(rlo[2], rlo[3]);
    p.z = packbf2(rlo[4], rlo[5]); p.w = packbf2(rlo[6], rlo[7]);
    *(uint4*)(xr + 768) = p;
}

// ---------------------------------------------------------------------------
// Kernel B: bf16 tensor-core GEMM, virtual K=1536. BM=64, BN=64, BK=64.
// 256 threads (8 warps: 2 wm x 4 wn, warp tile 32x16). 3-stage cp.async,
// one barrier per k-tile, grid 128x4 = 512 CTAs, dyn smem 55.3 KB.
// ---------------------------------------------------------------------------
#define BM 64
#define BN 64
#define BK 64
#define LDSK 72                 // 64 bf16 + 16B pad -> ldmatrix conflict-free
#define STG (BM * LDSK)         // 4608 elems per operand per stage

__device__ __forceinline__ void mma16816(float c[4], const uint32_t a[4],
                                         const uint32_t b0, const uint32_t b1) {
    asm volatile(
        "mma.sync.aligned.m16n8k16.row.col.f32.bf16.bf16.f32 "
        "{%0,%1,%2,%3}, {%4,%5,%6,%7}, {%8,%9}, {%0,%1,%2,%3};\n"
        : "+f"(c[0]), "+f"(c[1]), "+f"(c[2]), "+f"(c[3])
        : "r"(a[0]), "r"(a[1]), "r"(a[2]), "r"(a[3]), "r"(b0), "r"(b1));
}

// virtual k-tile (BK=64, 24 tiles) -> A offset:
//  0..7: hi*Whi, 8..15: hi*Wlo, 16..23: lo*Whi
__device__ __forceinline__ int a_koff(int kt) {
    return (kt < 8) ? kt * BK : (kt < 16) ? (kt - 8) * BK
                                          : 512 + (kt - 16) * BK;
}

__global__ __launch_bounds__(256)
void gate_gemm_bf16(const float* __restrict__ h_tilde,
                    const float* __restrict__ Wg_b,
                    const float* __restrict__ Ug_b,
                    const float* __restrict__ b_g,
                    const int* __restrict__ lengths,
                    float* __restrict__ out) {
    extern __shared__ __align__(16) __nv_bfloat16 smem[];
    __nv_bfloat16* sA = smem;              // 3 * 4608
    __nv_bfloat16* sB = smem + 3 * STG;    // 3 * 4608

    const int tid  = threadIdx.x;
    const int warp = tid >> 5;
    const int lane = tid & 31;
    const int gq   = lane >> 2;
    const int t    = lane & 3;
    const int wm   = warp >> 2;       // 0..1
    const int wn   = warp & 3;        // 0..3
    const int bm0  = blockIdx.x * BM;
    const int bn0  = blockIdx.y * BN;

    float acc[2][2][4];
#pragma unroll
    for (int mt = 0; mt < 2; ++mt)
#pragma unroll
        for (int nt = 0; nt < 2; ++nt)
#pragma unroll
            for (int i = 0; i < 4; ++i) acc[mt][nt][i] = 0.f;

    const __nv_bfloat16* gA = g_Xc + (size_t)bm0 * K1;
    const __nv_bfloat16* gB = g_Wc + (size_t)bn0 * K2;

    const int lr = tid >> 2;            // 0..63
    const int c0 = (tid & 3) * 8;       // first 16B chunk
    const int c1 = c0 + 32;             // second 16B chunk

    // prime k-tiles 0,1
#pragma unroll
    for (int p = 0; p < 2; ++p) {
        const int ao = a_koff(p), bo = p * BK;
        cp_async16(sA + p * STG + lr * LDSK + c0, gA + (size_t)lr * K1 + ao + c0);
        cp_async16(sA + p * STG + lr * LDSK + c1, gA + (size_t)lr * K1 + ao + c1);
        cp_async16(sB + p * STG + lr * LDSK + c0, gB + (size_t)lr * K2 + bo + c0);
        cp_async16(sB + p * STG + lr * LDSK + c1, gB + (size_t)lr * K2 + bo + c1);
        cp_commit();
    }

    const int lmrow = lane & 15;
    const int lmcol = (lane >> 4) * 8;

    const int NKT = K2 / BK;   // 24
    for (int kt = 0; kt < NKT; ++kt) {
        cp_wait<1>();
        __syncthreads();   // tile kt visible; slot (kt+2)%3 reader-free

        const int pc = kt + 2;
        if (pc < NKT) {
            const int st = pc % 3;
            const int ao = a_koff(pc), bo = pc * BK;
            cp_async16(sA + st * STG + lr * LDSK + c0, gA + (size_t)lr * K1 + ao + c0);
            cp_async16(sA + st * STG + lr * LDSK + c1, gA + (size_t)lr * K1 + ao + c1);
            cp_async16(sB + st * STG + lr * LDSK + c0, gB + (size_t)lr * K2 + bo + c0);
            cp_async16(sB + st * STG + lr * LDSK + c1, gB + (size_t)lr * K2 + bo + c1);
        }
        cp_commit();

        const __nv_bfloat16* A  = sA + (kt % 3) * STG;
        const __nv_bfloat16* Bs = sB + (kt % 3) * STG;

#pragma unroll
        for (int ks = 0; ks < 4; ++ks) {
            uint32_t af[2][4], bf[4];
#pragma unroll
            for (int mt = 0; mt < 2; ++mt)
                ldsm_x4(af[mt],
                        A + (wm * 32 + mt * 16 + lmrow) * LDSK + ks * 16 + lmcol);
            ldsm_x4(bf, Bs + (wn * 16 + lmrow) * LDSK + ks * 16 + lmcol);
#pragma unroll
            for (int mt = 0; mt < 2; ++mt) {
                mma16816(acc[mt][0], af[mt], bf[0], bf[2]);
                mma16816(acc[mt][1], af[mt], bf[1], bf[3]);
            }
        }
    }

    // fused epilogue
#pragma unroll
    for (int nt = 0; nt < 2; ++nt) {
        const int n = bn0 + wn * 16 + nt * 8 + 2 * t;
        const float bi0 = Wg_b[n] + Ug_b[n] + b_g[n];
        const float bi1 = Wg_b[n + 1] + Ug_b[n + 1] + b_g[n + 1];
#pragma unroll
        for (int mt = 0; mt < 2; ++mt) {
#pragma unroll
            for (int h2 = 0; h2 < 2; ++h2) {
                const int row = bm0 + wm * 32 + mt * 16 + gq + 8 * h2;
                const bool has = lengths[row] > 0;
                const size_t base = (size_t)row * D_SZ + n;
                const float2 rv = *(const float2*)(g_r + base);
                const float2 hv = *(const float2*)(h_tilde + base);
                const float z0 = acc[mt][nt][2 * h2 + 0] + bi0;
                const float z1 = acc[mt][nt][2 * h2 + 1] + bi1;
                const float g0 = 1.f / (1.f + __expf(-z0));
                const float g1 = 1.f / (1.f + __expf(-z1));
                const float o0 = has ? (g0 * rv.x + (1.f - g0) * hv.x) : hv.x;
                const float o1 = has ? (g1 * rv.y + (1.f - g1) * hv.y) : hv.y;
                *(float2*)(out + base) = make_float2(o0, o1);
            }
        }
    }
}

// ---------------------------------------------------------------------------
extern "C" void kernel_launch(void* const* d_in, const int* in_sizes, int n_in,
                              void* d_out, int out_size) {
    const float* h_tilde = (const float*)d_in[0];
    const float* mem     = (const float*)d_in[1];
    const int*   lengths = (const int*)d_in[2];
    const float* Wg_w    = (const float*)d_in[3];
    const float* Wg_b    = (const float*)d_in[4];
    const float* Ug_w    = (const float*)d_in[5];
    const float* Ug_b    = (const float*)d_in[6];
    const float* b_g     = (const float*)d_in[7];
    float* out = (float*)d_out;

    attn_r_kernel<<<B_SZ / 4, 128>>>(h_tilde, mem, lengths, Wg_w, Ug_w);

    const int smem_b = 6 * STG * (int)sizeof(__nv_bfloat16);  // 55296
    cudaFuncSetAttribute(gate_gemm_bf16,
                         cudaFuncAttributeMaxDynamicSharedMemorySize, smem_b);
    dim3 gridB(B_SZ / BM, D_SZ / BN);   // 128 x 4
    gate_gemm_bf16<<<gridB, 256, smem_b>>>(h_tilde, Wg_b, Ug_b, b_g,
                                           lengths, out);
}